// round 9
// baseline (speedup 1.0000x reference)
#include <cuda_runtime.h>
#include <cuda_bf16.h>
#include <cstdint>
#include <cstddef>

#define BATCH  4096
#define INDIM  1024
#define HDIM   1024
#define KDIM   2048
#define NGATE4 4096              // 4 * HDIM

// GEMM tiling
#define BM 256
#define BN 128
#define BK 16
#define NKIT (KDIM / BK)         // 128
#define GTHREADS 512             // 16 warps, warp grid 4(rows) x 4(cols), warp tile 64x32
#define NSTAGE 4

// smem strides (floats), padded: conflict-free for fragment lanes + 16B aligned
#define ASTRIDE 20               // BK + 4
#define BSTRIDE 136              // BN + 8
#define A_STAGE_BYTES (BM * ASTRIDE * 4)              // 20480
#define B_STAGE_BYTES (BK * BSTRIDE * 4)              // 8704
#define STAGE_BYTES   (A_STAGE_BYTES + B_STAGE_BYTES) // 29184
#define SMEM_TOTAL    (NSTAGE * STAGE_BYTES)          // 116736

// 64 MB gates scratch: gates[m][4096], gate g occupies cols [g*1024, (g+1)*1024)
__device__ float g_gates[(size_t)BATCH * NGATE4];

__device__ __forceinline__ uint32_t smem_u32(const void* p) {
    uint32_t a;
    asm("{ .reg .u64 t; cvta.to.shared.u64 t, %1; cvt.u32.u64 %0, t; }" : "=r"(a) : "l"(p));
    return a;
}
__device__ __forceinline__ uint32_t f2tf32(float f) {
    uint32_t r;
    asm("cvt.rna.tf32.f32 %0, %1;" : "=r"(r) : "f"(f));
    return r;
}
__device__ __forceinline__ void mma_tf32(float* c, const uint32_t* a, const uint32_t* b) {
    asm volatile(
        "mma.sync.aligned.m16n8k8.row.col.f32.tf32.tf32.f32 "
        "{%0,%1,%2,%3}, {%4,%5,%6,%7}, {%8,%9}, {%0,%1,%2,%3};"
        : "+f"(c[0]), "+f"(c[1]), "+f"(c[2]), "+f"(c[3])
        : "r"(a[0]), "r"(a[1]), "r"(a[2]), "r"(a[3]), "r"(b[0]), "r"(b[1]));
}
#define CP_ASYNC16(sa, gp) \
    asm volatile("cp.async.cg.shared.global [%0], [%1], 16;" :: "r"(sa), "l"(gp) : "memory")
#define CP_COMMIT() asm volatile("cp.async.commit_group;" ::: "memory")

// ---------------------------------------------------------------------------
// GEMM: gates = [x | h_prev] @ [Wf Wi Wg Wo]   (tf32 mma.sync, fp32 accum)
// ---------------------------------------------------------------------------
__device__ __forceinline__ void load_stage(char* smem, int s, int kbase, int m0,
                                           const float* __restrict__ x,
                                           const float* __restrict__ h_prev,
                                           const float* __restrict__ Wsel,
                                           int colbase, int tid) {
    uint32_t abase = smem_u32(smem + (size_t)s * STAGE_BYTES);
    uint32_t bbase = abase + A_STAGE_BYTES;
    // A: BM x BK = 1024 16B-chunks, 512 threads -> 2 each
    #pragma unroll
    for (int t = 0; t < 2; ++t) {
        int c = tid + t * GTHREADS;           // 0..1023
        int row = c >> 2;                     // 0..255
        int kq  = (c & 3) * 4;                // 0,4,8,12
        int gk  = kbase + kq;
        const float* gp = (gk < INDIM)
            ? (x      + (size_t)(m0 + row) * INDIM + gk)
            : (h_prev + (size_t)(m0 + row) * HDIM  + (gk - INDIM));
        CP_ASYNC16(abase + (uint32_t)(row * ASTRIDE + kq) * 4, gp);
    }
    // B: BK x BN = 512 16B-chunks, 1 each
    {
        int c = tid;                          // 0..511
        int kr = c >> 5;                      // 0..15
        int nq = (c & 31) * 4;                // 0..124
        const float* gp = Wsel + (size_t)(kbase + kr) * HDIM + colbase + nq;
        CP_ASYNC16(bbase + (uint32_t)(kr * BSTRIDE + nq) * 4, gp);
    }
}

__global__ __launch_bounds__(GTHREADS, 1)
void gates_gemm_kernel(const float* __restrict__ x, const float* __restrict__ h_prev,
                       const float* __restrict__ Wf, const float* __restrict__ Wi,
                       const float* __restrict__ Wg, const float* __restrict__ Wo) {
    extern __shared__ char smem[];
    int tid  = threadIdx.x;
    int wid  = tid >> 5;
    int lane = tid & 31;
    int wr = wid >> 2;                 // 0..3  (64-row slice)
    int wc = wid & 3;                  // 0..3  (32-col slice)

    int mt = (int)(blockIdx.x >> 5);   // 0..15
    int nt = (int)(blockIdx.x & 31);   // 0..31
    int m0 = mt * BM;
    int n0 = nt * BN;                  // global col in [0,4096)
    int gate = n0 >> 10;
    int colbase = n0 & 1023;
    const float* Wsel = (gate == 0) ? Wf : (gate == 1) ? Wi : (gate == 2) ? Wg : Wo;

    float acc[4][4][4];
    #pragma unroll
    for (int mi = 0; mi < 4; ++mi)
        #pragma unroll
        for (int nj = 0; nj < 4; ++nj)
            #pragma unroll
            for (int e = 0; e < 4; ++e) acc[mi][nj][e] = 0.0f;

    // prologue: NSTAGE-1 = 3 stages in flight
    load_stage(smem, 0, 0,      m0, x, h_prev, Wsel, colbase, tid); CP_COMMIT();
    load_stage(smem, 1, BK,     m0, x, h_prev, Wsel, colbase, tid); CP_COMMIT();
    load_stage(smem, 2, 2 * BK, m0, x, h_prev, Wsel, colbase, tid); CP_COMMIT();

    int rbase = lane >> 2;             // 0..7
    int kk    = lane & 3;              // 0..3

    for (int it = 0; it < NKIT; ++it) {
        if (it + 2 < NKIT)      asm volatile("cp.async.wait_group 2;" ::: "memory");
        else if (it + 1 < NKIT) asm volatile("cp.async.wait_group 1;" ::: "memory");
        else                    asm volatile("cp.async.wait_group 0;" ::: "memory");
        __syncthreads();

        if (it + 3 < NKIT) {
            load_stage(smem, (it + 3) % NSTAGE, (it + 3) * BK, m0, x, h_prev, Wsel, colbase, tid);
            CP_COMMIT();
        }

        const float* As = (const float*)(smem + (size_t)(it % NSTAGE) * STAGE_BYTES);
        const float* Bs = (const float*)(smem + (size_t)(it % NSTAGE) * STAGE_BYTES + A_STAGE_BYTES);

        #pragma unroll
        for (int k8 = 0; k8 < BK; k8 += 8) {
            uint32_t af[4][4], bf2[4][2];
            #pragma unroll
            for (int mi = 0; mi < 4; ++mi) {
                int r = wr * 64 + mi * 16 + rbase;
                af[mi][0] = f2tf32(As[(r    ) * ASTRIDE + k8 + kk    ]);
                af[mi][1] = f2tf32(As[(r + 8) * ASTRIDE + k8 + kk    ]);
                af[mi][2] = f2tf32(As[(r    ) * ASTRIDE + k8 + kk + 4]);
                af[mi][3] = f2tf32(As[(r + 8) * ASTRIDE + k8 + kk + 4]);
            }
            #pragma unroll
            for (int nj = 0; nj < 4; ++nj) {
                int n = wc * 32 + nj * 8 + rbase;
                bf2[nj][0] = f2tf32(Bs[(k8 + kk    ) * BSTRIDE + n]);
                bf2[nj][1] = f2tf32(Bs[(k8 + kk + 4) * BSTRIDE + n]);
            }
            #pragma unroll
            for (int mi = 0; mi < 4; ++mi)
                #pragma unroll
                for (int nj = 0; nj < 4; ++nj)
                    mma_tf32(acc[mi][nj], af[mi], bf2[nj]);
        }
    }

    // write accumulators to gates scratch
    int crow = (lane >> 2);
    int ccol = (lane & 3) * 2;
    #pragma unroll
    for (int mi = 0; mi < 4; ++mi) {
        int r0 = m0 + wr * 64 + mi * 16 + crow;
        #pragma unroll
        for (int nj = 0; nj < 4; ++nj) {
            int col = n0 + wc * 32 + nj * 8 + ccol;
            *(float2*)(g_gates + (size_t)r0 * NGATE4 + col) =
                make_float2(acc[mi][nj][0], acc[mi][nj][1]);
            *(float2*)(g_gates + (size_t)(r0 + 8) * NGATE4 + col) =
                make_float2(acc[mi][nj][2], acc[mi][nj][3]);
        }
    }
}

// ---------------------------------------------------------------------------
// Fused LSTM pointwise: f,i,g,o -> (h_next, c_next)
// ---------------------------------------------------------------------------
__global__ __launch_bounds__(256)
void lstm_pointwise_kernel(const float* __restrict__ c_prev,
                           const float* __restrict__ bfb, const float* __restrict__ bib,
                           const float* __restrict__ bgb, const float* __restrict__ bob,
                           float* __restrict__ h_out, float* __restrict__ c_out) {
    int i = blockIdx.x * 256 + threadIdx.x;        // 0 .. 1M-1 float4 groups
    if (i >= (BATCH * HDIM) / 4) return;
    int m = i >> 8;                                 // 256 float4 per row
    int n = (i & 255) * 4;
    size_t gb = (size_t)m * NGATE4;

    float4 fv = *(const float4*)(g_gates + gb + 0 * HDIM + n);
    float4 iv = *(const float4*)(g_gates + gb + 1 * HDIM + n);
    float4 gv = *(const float4*)(g_gates + gb + 2 * HDIM + n);
    float4 ov = *(const float4*)(g_gates + gb + 3 * HDIM + n);
    float4 bfv = *(const float4*)(bfb + n);
    float4 biv = *(const float4*)(bib + n);
    float4 bgv = *(const float4*)(bgb + n);
    float4 bov = *(const float4*)(bob + n);
    float4 cv = *(const float4*)(c_prev + (size_t)m * HDIM + n);

    float fa[4] = {fv.x + bfv.x, fv.y + bfv.y, fv.z + bfv.z, fv.w + bfv.w};
    float ia[4] = {iv.x + biv.x, iv.y + biv.y, iv.z + biv.z, iv.w + biv.w};
    float ga[4] = {gv.x + bgv.x, gv.y + bgv.y, gv.z + bgv.z, gv.w + bgv.w};
    float oa[4] = {ov.x + bov.x, ov.y + bov.y, ov.z + bov.z, ov.w + bov.w};
    float ca[4] = {cv.x, cv.y, cv.z, cv.w};
    float hn[4], cn[4];
    #pragma unroll
    for (int e = 0; e < 4; ++e) {
        float F = 1.0f / (1.0f + __expf(-fa[e]));
        float I = 1.0f / (1.0f + __expf(-ia[e]));
        float G = tanhf(ga[e]);
        float O = 1.0f / (1.0f + __expf(-oa[e]));
        float c = F * ca[e] + I * G;
        cn[e] = c;
        hn[e] = O * tanhf(c);
    }
    *(float4*)(h_out + (size_t)m * HDIM + n) = make_float4(hn[0], hn[1], hn[2], hn[3]);
    *(float4*)(c_out + (size_t)m * HDIM + n) = make_float4(cn[0], cn[1], cn[2], cn[3]);
}

// ---------------------------------------------------------------------------
extern "C" void kernel_launch(void* const* d_in, const int* in_sizes, int n_in,
                              void* d_out, int out_size) {
    (void)in_sizes; (void)n_in; (void)out_size;
    const float* x      = (const float*)d_in[0];
    const float* h_prev = (const float*)d_in[1];
    const float* c_prev = (const float*)d_in[2];
    const float* Wf     = (const float*)d_in[3];
    const float* bfb    = (const float*)d_in[4];
    const float* Wi     = (const float*)d_in[5];
    const float* bib    = (const float*)d_in[6];
    const float* Wg     = (const float*)d_in[7];
    const float* bgb    = (const float*)d_in[8];
    const float* Wo     = (const float*)d_in[9];
    const float* bob    = (const float*)d_in[10];
    float* h_out = (float*)d_out;                          // [B, H]
    float* c_out = (float*)d_out + (size_t)BATCH * HDIM;   // [B, H]

    cudaFuncSetAttribute(gates_gemm_kernel,
                         cudaFuncAttributeMaxDynamicSharedMemorySize, SMEM_TOTAL);

    int grid = (BATCH / BM) * (NGATE4 / BN);   // 16 * 32 = 512
    gates_gemm_kernel<<<grid, GTHREADS, SMEM_TOTAL>>>(x, h_prev, Wf, Wi, Wg, Wo);

    int pgrid = (BATCH * HDIM / 4) / 256;      // 4096
    lstm_pointwise_kernel<<<pgrid, 256>>>(c_prev, bfb, bib, bgb, bob, h_out, c_out);
}

// round 12
// speedup vs baseline: 1.3370x; 1.3370x over previous
#include <cuda_runtime.h>
#include <cuda_bf16.h>
#include <cstdint>
#include <cstddef>

#define BATCH  4096
#define INDIM  1024
#define HDIM   1024
#define KDIM   2048
#define NGATE4 4096              // 4 * HDIM

// GEMM tiling
#define BM 128
#define BN 128
#define BK 16
#define NKIT (KDIM / BK)         // 128
#define GTHREADS 256             // 8 warps, warp grid 2(rows) x 4(cols), warp tile 64x32
#define NSTAGE 3

// smem strides (floats), padded: conflict-free for fragment lanes + 16B aligned
#define ASTRIDE 20               // BK + 4
#define BSTRIDE 136              // BN + 8
#define A_STAGE_BYTES (BM * ASTRIDE * 4)              // 10240
#define B_STAGE_BYTES (BK * BSTRIDE * 4)              // 8704
#define STAGE_BYTES   (A_STAGE_BYTES + B_STAGE_BYTES) // 18944
#define SMEM_TOTAL    (NSTAGE * STAGE_BYTES)          // 56832  (x2 CTAs = 113664)

// 64 MB gates scratch: gates[m][4096], gate g occupies cols [g*1024, (g+1)*1024)
__device__ float g_gates[(size_t)BATCH * NGATE4];

__device__ __forceinline__ uint32_t smem_u32(const void* p) {
    uint32_t a;
    asm("{ .reg .u64 t; cvta.to.shared.u64 t, %1; cvt.u32.u64 %0, t; }" : "=r"(a) : "l"(p));
    return a;
}
__device__ __forceinline__ uint32_t f2tf32(float f) {
    uint32_t r;
    asm("cvt.rna.tf32.f32 %0, %1;" : "=r"(r) : "f"(f));
    return r;
}
__device__ __forceinline__ void mma_tf32(float* c, const uint32_t* a, const uint32_t* b) {
    asm volatile(
        "mma.sync.aligned.m16n8k8.row.col.f32.tf32.tf32.f32 "
        "{%0,%1,%2,%3}, {%4,%5,%6,%7}, {%8,%9}, {%0,%1,%2,%3};"
        : "+f"(c[0]), "+f"(c[1]), "+f"(c[2]), "+f"(c[3])
        : "r"(a[0]), "r"(a[1]), "r"(a[2]), "r"(a[3]), "r"(b[0]), "r"(b[1]));
}
#define CP_ASYNC16(sa, gp) \
    asm volatile("cp.async.cg.shared.global [%0], [%1], 16;" :: "r"(sa), "l"(gp) : "memory")
#define CP_COMMIT() asm volatile("cp.async.commit_group;" ::: "memory")

// ---------------------------------------------------------------------------
// GEMM: gates = [x | h_prev] @ [Wf Wi Wg Wo]   (tf32 mma.sync, fp32 accum)
// ---------------------------------------------------------------------------
__device__ __forceinline__ void load_stage(char* smem, int s, int kbase, int m0,
                                           const float* __restrict__ x,
                                           const float* __restrict__ h_prev,
                                           const float* __restrict__ Wsel,
                                           int colbase, int tid) {
    uint32_t abase = smem_u32(smem + (size_t)s * STAGE_BYTES);
    uint32_t bbase = abase + A_STAGE_BYTES;
    // A: BM x BK = 512 16B-chunks, 256 threads -> 2 each
    #pragma unroll
    for (int t = 0; t < 2; ++t) {
        int c = tid + t * GTHREADS;           // 0..511
        int row = c >> 2;                     // 0..127
        int kq  = (c & 3) * 4;                // 0,4,8,12
        int gk  = kbase + kq;
        const float* gp = (gk < INDIM)
            ? (x      + (size_t)(m0 + row) * INDIM + gk)
            : (h_prev + (size_t)(m0 + row) * HDIM  + (gk - INDIM));
        CP_ASYNC16(abase + (uint32_t)(row * ASTRIDE + kq) * 4, gp);
    }
    // B: BK x BN = 512 16B-chunks, 2 each
    #pragma unroll
    for (int t = 0; t < 2; ++t) {
        int c = tid + t * GTHREADS;           // 0..511
        int kr = c >> 5;                      // 0..15
        int nq = (c & 31) * 4;                // 0..124
        const float* gp = Wsel + (size_t)(kbase + kr) * HDIM + colbase + nq;
        CP_ASYNC16(bbase + (uint32_t)(kr * BSTRIDE + nq) * 4, gp);
    }
}

__global__ __launch_bounds__(GTHREADS, 2)
void gates_gemm_kernel(const float* __restrict__ x, const float* __restrict__ h_prev,
                       const float* __restrict__ Wf, const float* __restrict__ Wi,
                       const float* __restrict__ Wg, const float* __restrict__ Wo) {
    extern __shared__ char smem[];
    int tid  = threadIdx.x;
    int wid  = tid >> 5;
    int lane = tid & 31;
    int wr = wid >> 2;                 // 0..1  (64-row slice)
    int wc = wid & 3;                  // 0..3  (32-col slice)

    int mt = (int)(blockIdx.x >> 5);   // 0..31
    int nt = (int)(blockIdx.x & 31);   // 0..31
    int m0 = mt * BM;
    int n0 = nt * BN;                  // global col in [0,4096)
    int gate = n0 >> 10;
    int colbase = n0 & 1023;
    const float* Wsel = (gate == 0) ? Wf : (gate == 1) ? Wi : (gate == 2) ? Wg : Wo;

    float acc[4][4][4];
    #pragma unroll
    for (int mi = 0; mi < 4; ++mi)
        #pragma unroll
        for (int nj = 0; nj < 4; ++nj)
            #pragma unroll
            for (int e = 0; e < 4; ++e) acc[mi][nj][e] = 0.0f;

    // prologue: 2 stages in flight
    load_stage(smem, 0, 0,  m0, x, h_prev, Wsel, colbase, tid); CP_COMMIT();
    load_stage(smem, 1, BK, m0, x, h_prev, Wsel, colbase, tid); CP_COMMIT();

    int rbase = lane >> 2;             // 0..7
    int kk    = lane & 3;              // 0..3

    for (int it = 0; it < NKIT; ++it) {
        if (it + 1 < NKIT) asm volatile("cp.async.wait_group 1;" ::: "memory");
        else               asm volatile("cp.async.wait_group 0;" ::: "memory");
        __syncthreads();

        if (it + 2 < NKIT) {
            load_stage(smem, (it + 2) % NSTAGE, (it + 2) * BK, m0, x, h_prev, Wsel, colbase, tid);
            CP_COMMIT();
        }

        const float* As = (const float*)(smem + (size_t)(it % NSTAGE) * STAGE_BYTES);
        const float* Bs = (const float*)(smem + (size_t)(it % NSTAGE) * STAGE_BYTES + A_STAGE_BYTES);

        #pragma unroll
        for (int k8 = 0; k8 < BK; k8 += 8) {
            uint32_t af[4][4], bf2[4][2];
            #pragma unroll
            for (int mi = 0; mi < 4; ++mi) {
                int r = wr * 64 + mi * 16 + rbase;
                af[mi][0] = f2tf32(As[(r    ) * ASTRIDE + k8 + kk    ]);
                af[mi][1] = f2tf32(As[(r + 8) * ASTRIDE + k8 + kk    ]);
                af[mi][2] = f2tf32(As[(r    ) * ASTRIDE + k8 + kk + 4]);
                af[mi][3] = f2tf32(As[(r + 8) * ASTRIDE + k8 + kk + 4]);
            }
            #pragma unroll
            for (int nj = 0; nj < 4; ++nj) {
                int n = wc * 32 + nj * 8 + rbase;
                bf2[nj][0] = f2tf32(Bs[(k8 + kk    ) * BSTRIDE + n]);
                bf2[nj][1] = f2tf32(Bs[(k8 + kk + 4) * BSTRIDE + n]);
            }
            #pragma unroll
            for (int mi = 0; mi < 4; ++mi)
                #pragma unroll
                for (int nj = 0; nj < 4; ++nj)
                    mma_tf32(acc[mi][nj], af[mi], bf2[nj]);
        }
    }

    // write accumulators to gates scratch
    int crow = (lane >> 2);
    int ccol = (lane & 3) * 2;
    #pragma unroll
    for (int mi = 0; mi < 4; ++mi) {
        int r0 = m0 + wr * 64 + mi * 16 + crow;
        #pragma unroll
        for (int nj = 0; nj < 4; ++nj) {
            int col = n0 + wc * 32 + nj * 8 + ccol;
            *(float2*)(g_gates + (size_t)r0 * NGATE4 + col) =
                make_float2(acc[mi][nj][0], acc[mi][nj][1]);
            *(float2*)(g_gates + (size_t)(r0 + 8) * NGATE4 + col) =
                make_float2(acc[mi][nj][2], acc[mi][nj][3]);
        }
    }
}

// ---------------------------------------------------------------------------
// Fused LSTM pointwise: f,i,g,o -> (h_next, c_next)
// ---------------------------------------------------------------------------
__global__ __launch_bounds__(256)
void lstm_pointwise_kernel(const float* __restrict__ c_prev,
                           const float* __restrict__ bfb, const float* __restrict__ bib,
                           const float* __restrict__ bgb, const float* __restrict__ bob,
                           float* __restrict__ h_out, float* __restrict__ c_out) {
    int i = blockIdx.x * 256 + threadIdx.x;        // 0 .. 1M-1 float4 groups
    if (i >= (BATCH * HDIM) / 4) return;
    int m = i >> 8;                                 // 256 float4 per row
    int n = (i & 255) * 4;
    size_t gb = (size_t)m * NGATE4;

    float4 fv = *(const float4*)(g_gates + gb + 0 * HDIM + n);
    float4 iv = *(const float4*)(g_gates + gb + 1 * HDIM + n);
    float4 gv = *(const float4*)(g_gates + gb + 2 * HDIM + n);
    float4 ov = *(const float4*)(g_gates + gb + 3 * HDIM + n);
    float4 bfv = *(const float4*)(bfb + n);
    float4 biv = *(const float4*)(bib + n);
    float4 bgv = *(const float4*)(bgb + n);
    float4 bov = *(const float4*)(bob + n);
    float4 cv = *(const float4*)(c_prev + (size_t)m * HDIM + n);

    float fa[4] = {fv.x + bfv.x, fv.y + bfv.y, fv.z + bfv.z, fv.w + bfv.w};
    float ia[4] = {iv.x + biv.x, iv.y + biv.y, iv.z + biv.z, iv.w + biv.w};
    float ga[4] = {gv.x + bgv.x, gv.y + bgv.y, gv.z + bgv.z, gv.w + bgv.w};
    float oa[4] = {ov.x + bov.x, ov.y + bov.y, ov.z + bov.z, ov.w + bov.w};
    float ca[4] = {cv.x, cv.y, cv.z, cv.w};
    float hn[4], cn[4];
    #pragma unroll
    for (int e = 0; e < 4; ++e) {
        float F = 1.0f / (1.0f + __expf(-fa[e]));
        float I = 1.0f / (1.0f + __expf(-ia[e]));
        float G = tanhf(ga[e]);
        float O = 1.0f / (1.0f + __expf(-oa[e]));
        float c = F * ca[e] + I * G;
        cn[e] = c;
        hn[e] = O * tanhf(c);
    }
    *(float4*)(h_out + (size_t)m * HDIM + n) = make_float4(hn[0], hn[1], hn[2], hn[3]);
    *(float4*)(c_out + (size_t)m * HDIM + n) = make_float4(cn[0], cn[1], cn[2], cn[3]);
}

// ---------------------------------------------------------------------------
extern "C" void kernel_launch(void* const* d_in, const int* in_sizes, int n_in,
                              void* d_out, int out_size) {
    (void)in_sizes; (void)n_in; (void)out_size;
    const float* x      = (const float*)d_in[0];
    const float* h_prev = (const float*)d_in[1];
    const float* c_prev = (const float*)d_in[2];
    const float* Wf     = (const float*)d_in[3];
    const float* bfb    = (const float*)d_in[4];
    const float* Wi     = (const float*)d_in[5];
    const float* bib    = (const float*)d_in[6];
    const float* Wg     = (const float*)d_in[7];
    const float* bgb    = (const float*)d_in[8];
    const float* Wo     = (const float*)d_in[9];
    const float* bob    = (const float*)d_in[10];
    float* h_out = (float*)d_out;                          // [B, H]
    float* c_out = (float*)d_out + (size_t)BATCH * HDIM;   // [B, H]

    cudaFuncSetAttribute(gates_gemm_kernel,
                         cudaFuncAttributeMaxDynamicSharedMemorySize, SMEM_TOTAL);

    int grid = (BATCH / BM) * (NGATE4 / BN);   // 32 * 32 = 1024
    gates_gemm_kernel<<<grid, GTHREADS, SMEM_TOTAL>>>(x, h_prev, Wf, Wi, Wg, Wo);

    int pgrid = (BATCH * HDIM / 4) / 256;      // 4096
    lstm_pointwise_kernel<<<pgrid, 256>>>(c_prev, bfb, bib, bgb, bob, h_out, c_out);
}

// round 13
// speedup vs baseline: 1.9013x; 1.4220x over previous
#include <cuda_runtime.h>
#include <cuda_bf16.h>
#include <cstdint>
#include <cstddef>

#define BATCH  4096
#define INDIM  1024
#define HDIM   1024
#define KDIM   2048
#define NGATE4 4096              // 4 * HDIM

// GEMM tiling
#define BM 256
#define BN 128
#define BK 32
#define NKIT (KDIM / BK)         // 64
#define GTHREADS 256             // 8 warps, warp grid 4(rows) x 2(cols), warp tile 64x64
#define NSTAGE 3

// smem strides (floats), padded: conflict-free for fragment lanes + 16B aligned
#define ASTRIDE 36               // BK + 4
#define BSTRIDE 136              // BN + 8
#define A_STAGE_BYTES (BM * ASTRIDE * 4)              // 36864
#define B_STAGE_BYTES (BK * BSTRIDE * 4)              // 17408
#define STAGE_BYTES   (A_STAGE_BYTES + B_STAGE_BYTES) // 54272
#define SMEM_TOTAL    (NSTAGE * STAGE_BYTES)          // 162816

// 64 MB gates scratch: gates[m][4096], gate g occupies cols [g*1024, (g+1)*1024)
__device__ float g_gates[(size_t)BATCH * NGATE4];

__device__ __forceinline__ uint32_t smem_u32(const void* p) {
    uint32_t a;
    asm("{ .reg .u64 t; cvta.to.shared.u64 t, %1; cvt.u32.u64 %0, t; }" : "=r"(a) : "l"(p));
    return a;
}
__device__ __forceinline__ uint32_t f2tf32(float f) {
    uint32_t r;
    asm("cvt.rna.tf32.f32 %0, %1;" : "=r"(r) : "f"(f));
    return r;
}
__device__ __forceinline__ void mma_tf32(float* c, const uint32_t* a, const uint32_t* b) {
    asm volatile(
        "mma.sync.aligned.m16n8k8.row.col.f32.tf32.tf32.f32 "
        "{%0,%1,%2,%3}, {%4,%5,%6,%7}, {%8,%9}, {%0,%1,%2,%3};"
        : "+f"(c[0]), "+f"(c[1]), "+f"(c[2]), "+f"(c[3])
        : "r"(a[0]), "r"(a[1]), "r"(a[2]), "r"(a[3]), "r"(b[0]), "r"(b[1]));
}
#define CP_ASYNC16(sa, gp) \
    asm volatile("cp.async.cg.shared.global [%0], [%1], 16;" :: "r"(sa), "l"(gp) : "memory")
#define CP_COMMIT() asm volatile("cp.async.commit_group;" ::: "memory")

// ---------------------------------------------------------------------------
// GEMM: gates = [x | h_prev] @ [Wf Wi Wg Wo]   (tf32 mma.sync, fp32 accum)
// ---------------------------------------------------------------------------
__device__ __forceinline__ void load_stage(char* smem, int s, int kbase, int m0,
                                           const float* __restrict__ x,
                                           const float* __restrict__ h_prev,
                                           const float* __restrict__ Wsel,
                                           int colbase, int tid) {
    uint32_t abase = smem_u32(smem + (size_t)s * STAGE_BYTES);
    uint32_t bbase = abase + A_STAGE_BYTES;
    // whole stage comes from x or from h_prev (kbase is a multiple of BK=32)
    const float* Asrc = (kbase < INDIM) ? (x + kbase) : (h_prev + (kbase - INDIM));
    // A: BM x BK = 2048 16B-chunks, 256 threads -> 8 each
    #pragma unroll
    for (int t = 0; t < 8; ++t) {
        int c = tid + t * GTHREADS;           // 0..2047
        int row = c >> 3;                     // 0..255
        int kq  = (c & 7) * 4;                // 0..28
        CP_ASYNC16(abase + (uint32_t)(row * ASTRIDE + kq) * 4,
                   Asrc + (size_t)(m0 + row) * 1024 + kq);
    }
    // B: BK x BN = 1024 16B-chunks, 4 each
    #pragma unroll
    for (int t = 0; t < 4; ++t) {
        int c = tid + t * GTHREADS;           // 0..1023
        int kr = c >> 5;                      // 0..31
        int nq = (c & 31) * 4;                // 0..124
        CP_ASYNC16(bbase + (uint32_t)(kr * BSTRIDE + nq) * 4,
                   Wsel + (size_t)(kbase + kr) * HDIM + colbase + nq);
    }
}

__global__ __launch_bounds__(GTHREADS, 1)
void gates_gemm_kernel(const float* __restrict__ x, const float* __restrict__ h_prev,
                       const float* __restrict__ Wf, const float* __restrict__ Wi,
                       const float* __restrict__ Wg, const float* __restrict__ Wo) {
    extern __shared__ char smem[];
    int tid  = threadIdx.x;
    int wid  = tid >> 5;
    int lane = tid & 31;
    int wr = wid >> 1;                 // 0..3  (64-row slice)
    int wc = wid & 1;                  // 0..1  (64-col slice)

    int mt = (int)(blockIdx.x >> 5);   // 0..15
    int nt = (int)(blockIdx.x & 31);   // 0..31
    int m0 = mt * BM;
    int n0 = nt * BN;                  // global col in [0,4096)
    int gate = n0 >> 10;
    int colbase = n0 & 1023;
    const float* Wsel = (gate == 0) ? Wf : (gate == 1) ? Wi : (gate == 2) ? Wg : Wo;

    float acc[4][8][4];
    #pragma unroll
    for (int mi = 0; mi < 4; ++mi)
        #pragma unroll
        for (int nj = 0; nj < 8; ++nj)
            #pragma unroll
            for (int e = 0; e < 4; ++e) acc[mi][nj][e] = 0.0f;

    // prologue: 2 stages in flight
    load_stage(smem, 0, 0,  m0, x, h_prev, Wsel, colbase, tid); CP_COMMIT();
    load_stage(smem, 1, BK, m0, x, h_prev, Wsel, colbase, tid); CP_COMMIT();

    int rbase = lane >> 2;             // 0..7
    int kk    = lane & 3;              // 0..3

    for (int it = 0; it < NKIT; ++it) {
        if (it + 1 < NKIT) asm volatile("cp.async.wait_group 1;" ::: "memory");
        else               asm volatile("cp.async.wait_group 0;" ::: "memory");
        __syncthreads();

        if (it + 2 < NKIT) {
            load_stage(smem, (it + 2) % NSTAGE, (it + 2) * BK, m0, x, h_prev, Wsel, colbase, tid);
            CP_COMMIT();
        }

        const float* As = (const float*)(smem + (size_t)(it % NSTAGE) * STAGE_BYTES);
        const float* Bs = (const float*)(smem + (size_t)(it % NSTAGE) * STAGE_BYTES + A_STAGE_BYTES);

        // 4 independent k8 blocks -> intra-warp ILP for ptxas to pipeline
        #pragma unroll
        for (int k8 = 0; k8 < BK; k8 += 8) {
            uint32_t af[4][4], bf2[8][2];
            #pragma unroll
            for (int mi = 0; mi < 4; ++mi) {
                int r = wr * 64 + mi * 16 + rbase;
                af[mi][0] = f2tf32(As[(r    ) * ASTRIDE + k8 + kk    ]);
                af[mi][1] = f2tf32(As[(r + 8) * ASTRIDE + k8 + kk    ]);
                af[mi][2] = f2tf32(As[(r    ) * ASTRIDE + k8 + kk + 4]);
                af[mi][3] = f2tf32(As[(r + 8) * ASTRIDE + k8 + kk + 4]);
            }
            #pragma unroll
            for (int nj = 0; nj < 8; ++nj) {
                int n = wc * 64 + nj * 8 + rbase;
                bf2[nj][0] = f2tf32(Bs[(k8 + kk    ) * BSTRIDE + n]);
                bf2[nj][1] = f2tf32(Bs[(k8 + kk + 4) * BSTRIDE + n]);
            }
            #pragma unroll
            for (int mi = 0; mi < 4; ++mi)
                #pragma unroll
                for (int nj = 0; nj < 8; ++nj)
                    mma_tf32(acc[mi][nj], af[mi], bf2[nj]);
        }
    }

    // write accumulators to gates scratch
    int crow = (lane >> 2);
    int ccol = (lane & 3) * 2;
    #pragma unroll
    for (int mi = 0; mi < 4; ++mi) {
        int r0 = m0 + wr * 64 + mi * 16 + crow;
        #pragma unroll
        for (int nj = 0; nj < 8; ++nj) {
            int col = n0 + wc * 64 + nj * 8 + ccol;
            *(float2*)(g_gates + (size_t)r0 * NGATE4 + col) =
                make_float2(acc[mi][nj][0], acc[mi][nj][1]);
            *(float2*)(g_gates + (size_t)(r0 + 8) * NGATE4 + col) =
                make_float2(acc[mi][nj][2], acc[mi][nj][3]);
        }
    }
}

// ---------------------------------------------------------------------------
// Fused LSTM pointwise: f,i,g,o -> (h_next, c_next)
// ---------------------------------------------------------------------------
__global__ __launch_bounds__(256)
void lstm_pointwise_kernel(const float* __restrict__ c_prev,
                           const float* __restrict__ bfb, const float* __restrict__ bib,
                           const float* __restrict__ bgb, const float* __restrict__ bob,
                           float* __restrict__ h_out, float* __restrict__ c_out) {
    int i = blockIdx.x * 256 + threadIdx.x;        // 0 .. 1M-1 float4 groups
    if (i >= (BATCH * HDIM) / 4) return;
    int m = i >> 8;                                 // 256 float4 per row
    int n = (i & 255) * 4;
    size_t gb = (size_t)m * NGATE4;

    float4 fv = *(const float4*)(g_gates + gb + 0 * HDIM + n);
    float4 iv = *(const float4*)(g_gates + gb + 1 * HDIM + n);
    float4 gv = *(const float4*)(g_gates + gb + 2 * HDIM + n);
    float4 ov = *(const float4*)(g_gates + gb + 3 * HDIM + n);
    float4 bfv = *(const float4*)(bfb + n);
    float4 biv = *(const float4*)(bib + n);
    float4 bgv = *(const float4*)(bgb + n);
    float4 bov = *(const float4*)(bob + n);
    float4 cv = *(const float4*)(c_prev + (size_t)m * HDIM + n);

    float fa[4] = {fv.x + bfv.x, fv.y + bfv.y, fv.z + bfv.z, fv.w + bfv.w};
    float ia[4] = {iv.x + biv.x, iv.y + biv.y, iv.z + biv.z, iv.w + biv.w};
    float ga[4] = {gv.x + bgv.x, gv.y + bgv.y, gv.z + bgv.z, gv.w + bgv.w};
    float oa[4] = {ov.x + bov.x, ov.y + bov.y, ov.z + bov.z, ov.w + bov.w};
    float ca[4] = {cv.x, cv.y, cv.z, cv.w};
    float hn[4], cn[4];
    #pragma unroll
    for (int e = 0; e < 4; ++e) {
        float F = 1.0f / (1.0f + __expf(-fa[e]));
        float I = 1.0f / (1.0f + __expf(-ia[e]));
        float G = tanhf(ga[e]);
        float O = 1.0f / (1.0f + __expf(-oa[e]));
        float c = F * ca[e] + I * G;
        cn[e] = c;
        hn[e] = O * tanhf(c);
    }
    *(float4*)(h_out + (size_t)m * HDIM + n) = make_float4(hn[0], hn[1], hn[2], hn[3]);
    *(float4*)(c_out + (size_t)m * HDIM + n) = make_float4(cn[0], cn[1], cn[2], cn[3]);
}

// ---------------------------------------------------------------------------
extern "C" void kernel_launch(void* const* d_in, const int* in_sizes, int n_in,
                              void* d_out, int out_size) {
    (void)in_sizes; (void)n_in; (void)out_size;
    const float* x      = (const float*)d_in[0];
    const float* h_prev = (const float*)d_in[1];
    const float* c_prev = (const float*)d_in[2];
    const float* Wf     = (const float*)d_in[3];
    const float* bfb    = (const float*)d_in[4];
    const float* Wi     = (const float*)d_in[5];
    const float* bib    = (const float*)d_in[6];
    const float* Wg     = (const float*)d_in[7];
    const float* bgb    = (const float*)d_in[8];
    const float* Wo     = (const float*)d_in[9];
    const float* bob    = (const float*)d_in[10];
    float* h_out = (float*)d_out;                          // [B, H]
    float* c_out = (float*)d_out + (size_t)BATCH * HDIM;   // [B, H]

    cudaFuncSetAttribute(gates_gemm_kernel,
                         cudaFuncAttributeMaxDynamicSharedMemorySize, SMEM_TOTAL);

    int grid = (BATCH / BM) * (NGATE4 / BN);   // 16 * 32 = 512
    gates_gemm_kernel<<<grid, GTHREADS, SMEM_TOTAL>>>(x, h_prev, Wf, Wi, Wg, Wo);

    int pgrid = (BATCH * HDIM / 4) / 256;      // 4096
    lstm_pointwise_kernel<<<pgrid, 256>>>(c_prev, bfb, bib, bgb, bob, h_out, c_out);
}